// round 1
// baseline (speedup 1.0000x reference)
#include <cuda_runtime.h>
#include <math.h>

#define NN 50000
#define EE 400000
#define FF 32

// ---------------- scratch (static device allocations; harness-legal) ----------------
__device__ __align__(128) float g_e1[(size_t)EE * FF];
__device__ __align__(128) float g_e2[(size_t)EE * FF];
__device__ __align__(128) float g_e3[(size_t)EE * FF];
__device__ __align__(128) float g_acc1[(size_t)NN * FF];  // becomes x1 after finalize
__device__ __align__(128) float g_acc2[(size_t)NN * FF];  // becomes x2
__device__ __align__(128) float g_acc3[(size_t)NN * FF];  // becomes x3
__device__ __align__(128) float g_cnt[NN];

// ---------------- helpers ----------------
__device__ __forceinline__ void fmarow(float h[FF], float vk, const float* __restrict__ wr) {
#pragma unroll
    for (int j = 0; j < FF; j += 4) {
        float4 w = *(const float4*)(wr + j);
        h[j + 0] += vk * w.x;
        h[j + 1] += vk * w.y;
        h[j + 2] += vk * w.z;
        h[j + 3] += vk * w.w;
    }
}

// accumulate a 32-wide input segment (src, 16B aligned) against 32 rows of shared weights
__device__ __forceinline__ void seg32(float h[FF], const float* __restrict__ src,
                                      const float* __restrict__ ws) {
#pragma unroll
    for (int k = 0; k < FF; k += 4) {
        float4 v = *(const float4*)(src + k);
        fmarow(h, v.x, ws + (k + 0) * FF);
        fmarow(h, v.y, ws + (k + 1) * FF);
        fmarow(h, v.z, ws + (k + 2) * FF);
        fmarow(h, v.w, ws + (k + 3) * FF);
    }
}

__device__ __forceinline__ void cpsh(float* dst, const float* src, int n, int tid, int nt) {
    for (int i = tid; i < n; i += nt) dst[i] = src[i];
}

__device__ __forceinline__ void store_relu32(float* __restrict__ dst, const float o[FF]) {
#pragma unroll
    for (int j = 0; j < FF; j += 4) {
        float4 t = make_float4(fmaxf(o[j], 0.f), fmaxf(o[j + 1], 0.f),
                               fmaxf(o[j + 2], 0.f), fmaxf(o[j + 3], 0.f));
        *(float4*)(dst + j) = t;
    }
}

// ---------------- init / misc kernels ----------------
__global__ void k_zero() {
    int i = blockIdx.x * blockDim.x + threadIdx.x;
    if (i < NN * FF) {
        g_acc1[i] = 0.f;
        g_acc2[i] = 0.f;
        g_acc3[i] = 0.f;
    }
    if (i < NN) g_cnt[i] = 0.f;
}

__global__ void k_beta(const float* __restrict__ beta, float* __restrict__ out) {
    int i = blockIdx.x * blockDim.x + threadIdx.x;
    if (i < 3 * NN) out[(size_t)5 * EE + i] = beta[i];
}

__global__ void k_final(int which) {
    int i = blockIdx.x * blockDim.x + threadIdx.x;
    if (i >= NN * FF) return;
    float* acc = (which == 0) ? g_acc1 : (which == 1) ? g_acc2 : g_acc3;
    float c = fmaxf(g_cnt[i >> 5], 1.0f);
    acc[i] = fmaxf(acc[i] / c, 0.0f);
}

// ---------------- conv1: e1 = mlp2(edge_attr); scatter pre-relu; store relu ----------------
__global__ void k_conv1(const float* __restrict__ ea, const int* __restrict__ eidx,
                        const float* __restrict__ w10, const float* __restrict__ b10,
                        const float* __restrict__ w11, const float* __restrict__ b11) {
    __shared__ __align__(16) float s_w0[4 * FF];
    __shared__ __align__(16) float s_b0[FF];
    __shared__ __align__(16) float s_w1[FF * FF];
    __shared__ __align__(16) float s_b1[FF];
    int tid = threadIdx.x, nt = blockDim.x;
    cpsh(s_w0, w10, 4 * FF, tid, nt);
    cpsh(s_b0, b10, FF, tid, nt);
    cpsh(s_w1, w11, FF * FF, tid, nt);
    cpsh(s_b1, b11, FF, tid, nt);
    __syncthreads();

    int e = blockIdx.x * nt + tid;
    if (e >= EE) return;

    float4 a = *(const float4*)(ea + (size_t)e * 4);
    float h[FF];
#pragma unroll
    for (int j = 0; j < FF; j++) h[j] = s_b0[j];
    fmarow(h, a.x, s_w0);
    fmarow(h, a.y, s_w0 + FF);
    fmarow(h, a.z, s_w0 + 2 * FF);
    fmarow(h, a.w, s_w0 + 3 * FF);
#pragma unroll
    for (int j = 0; j < FF; j++) h[j] = fmaxf(h[j], 0.f);

    float o[FF];
#pragma unroll
    for (int j = 0; j < FF; j++) o[j] = s_b1[j];
#pragma unroll
    for (int k = 0; k < FF; k++) fmarow(o, h[k], s_w1 + k * FF);

    int r = eidx[e];
    float* acc = g_acc1 + (size_t)r * FF;
#pragma unroll
    for (int j = 0; j < FF; j++) atomicAdd(acc + j, o[j]);
    atomicAdd(&g_cnt[r], 1.0f);

    store_relu32(g_e1 + (size_t)e * FF, o);
}

// ---------------- conv2: in = [x1[r], x1[c], edge_attr, e1] (100) ----------------
__global__ void k_conv2(const float* __restrict__ ea, const int* __restrict__ eidx,
                        const float* __restrict__ w20, const float* __restrict__ b20,
                        const float* __restrict__ w21, const float* __restrict__ b21) {
    __shared__ __align__(16) float s_w0[100 * FF];
    __shared__ __align__(16) float s_b0[FF];
    __shared__ __align__(16) float s_w1[FF * FF];
    __shared__ __align__(16) float s_b1[FF];
    int tid = threadIdx.x, nt = blockDim.x;
    cpsh(s_w0, w20, 100 * FF, tid, nt);
    cpsh(s_b0, b20, FF, tid, nt);
    cpsh(s_w1, w21, FF * FF, tid, nt);
    cpsh(s_b1, b21, FF, tid, nt);
    __syncthreads();

    int e = blockIdx.x * nt + tid;
    if (e >= EE) return;

    int r = eidx[e], c = eidx[EE + e];
    float h[FF];
#pragma unroll
    for (int j = 0; j < FF; j++) h[j] = s_b0[j];
    seg32(h, g_acc1 + (size_t)r * FF, s_w0);             // rows 0..31 : x1[row]
    seg32(h, g_acc1 + (size_t)c * FF, s_w0 + 32 * FF);   // rows 32..63: x1[col]
    float4 a = *(const float4*)(ea + (size_t)e * 4);     // rows 64..67: edge_attr
    fmarow(h, a.x, s_w0 + 64 * FF);
    fmarow(h, a.y, s_w0 + 65 * FF);
    fmarow(h, a.z, s_w0 + 66 * FF);
    fmarow(h, a.w, s_w0 + 67 * FF);
    seg32(h, g_e1 + (size_t)e * FF, s_w0 + 68 * FF);     // rows 68..99: e1
#pragma unroll
    for (int j = 0; j < FF; j++) h[j] = fmaxf(h[j], 0.f);

    float o[FF];
#pragma unroll
    for (int j = 0; j < FF; j++) o[j] = s_b1[j];
#pragma unroll
    for (int k = 0; k < FF; k++) fmarow(o, h[k], s_w1 + k * FF);

    float* acc = g_acc2 + (size_t)r * FF;
#pragma unroll
    for (int j = 0; j < FF; j++) atomicAdd(acc + j, o[j]);

    store_relu32(g_e2 + (size_t)e * FF, o);
}

// ---------------- conv3: in = [x2[r], x1[r], x2[c], x1[c], e2, e1] (192) ----------------
__global__ void k_conv3(const int* __restrict__ eidx,
                        const float* __restrict__ w30, const float* __restrict__ b30,
                        const float* __restrict__ w31, const float* __restrict__ b31) {
    __shared__ __align__(16) float s_w0[192 * FF];
    __shared__ __align__(16) float s_b0[FF];
    __shared__ __align__(16) float s_w1[FF * FF];
    __shared__ __align__(16) float s_b1[FF];
    int tid = threadIdx.x, nt = blockDim.x;
    cpsh(s_w0, w30, 192 * FF, tid, nt);
    cpsh(s_b0, b30, FF, tid, nt);
    cpsh(s_w1, w31, FF * FF, tid, nt);
    cpsh(s_b1, b31, FF, tid, nt);
    __syncthreads();

    int e = blockIdx.x * nt + tid;
    if (e >= EE) return;

    int r = eidx[e], c = eidx[EE + e];
    float h[FF];
#pragma unroll
    for (int j = 0; j < FF; j++) h[j] = s_b0[j];
    seg32(h, g_acc2 + (size_t)r * FF, s_w0);              // x2[row]
    seg32(h, g_acc1 + (size_t)r * FF, s_w0 + 32 * FF);    // x1[row]
    seg32(h, g_acc2 + (size_t)c * FF, s_w0 + 64 * FF);    // x2[col]
    seg32(h, g_acc1 + (size_t)c * FF, s_w0 + 96 * FF);    // x1[col]
    seg32(h, g_e2 + (size_t)e * FF, s_w0 + 128 * FF);     // e2
    seg32(h, g_e1 + (size_t)e * FF, s_w0 + 160 * FF);     // e1
#pragma unroll
    for (int j = 0; j < FF; j++) h[j] = fmaxf(h[j], 0.f);

    float o[FF];
#pragma unroll
    for (int j = 0; j < FF; j++) o[j] = s_b1[j];
#pragma unroll
    for (int k = 0; k < FF; k++) fmarow(o, h[k], s_w1 + k * FF);

    float* acc = g_acc3 + (size_t)r * FF;
#pragma unroll
    for (int j = 0; j < FF; j++) atomicAdd(acc + j, o[j]);

    store_relu32(g_e3 + (size_t)e * FF, o);
}

// ---------------- conv4 + heads fused ----------------
__global__ void k_conv4(const float* __restrict__ ea, const int* __restrict__ eidx,
                        const float* __restrict__ w40, const float* __restrict__ b40,
                        const float* __restrict__ w41, const float* __restrict__ b41,
                        const float* __restrict__ wl01, const float* __restrict__ bl01,
                        const float* __restrict__ wl02, const float* __restrict__ bl02,
                        const float* __restrict__ wl1, const float* __restrict__ bl1,
                        const float* __restrict__ wl2, const float* __restrict__ bl2,
                        float* __restrict__ out) {
    __shared__ __align__(16) float s_w0[192 * FF];
    __shared__ __align__(16) float s_b0[FF];
    __shared__ __align__(16) float s_w1[FF * FF];
    __shared__ __align__(16) float s_b1[FF];
    __shared__ __align__(16) float s_w01[FF * FF];
    __shared__ __align__(16) float s_b01[FF];
    __shared__ __align__(16) float s_w02[FF * FF];
    __shared__ __align__(16) float s_b02[FF];
    __shared__ __align__(16) float s_wl1[FF * 4];
    __shared__ __align__(16) float s_wl2[FF];
    __shared__ float s_bl1[4];
    __shared__ float s_bl2;
    int tid = threadIdx.x, nt = blockDim.x;
    cpsh(s_w0, w40, 192 * FF, tid, nt);
    cpsh(s_b0, b40, FF, tid, nt);
    cpsh(s_w1, w41, FF * FF, tid, nt);
    cpsh(s_b1, b41, FF, tid, nt);
    cpsh(s_w01, wl01, FF * FF, tid, nt);
    cpsh(s_b01, bl01, FF, tid, nt);
    cpsh(s_w02, wl02, FF * FF, tid, nt);
    cpsh(s_b02, bl02, FF, tid, nt);
    cpsh(s_wl1, wl1, FF * 4, tid, nt);
    cpsh(s_wl2, wl2, FF, tid, nt);
    if (tid < 4) s_bl1[tid] = bl1[tid];
    if (tid == 0) s_bl2 = bl2[0];
    __syncthreads();

    int e = blockIdx.x * nt + tid;
    if (e >= EE) return;

    int r = eidx[e], c = eidx[EE + e];
    float h[FF];
#pragma unroll
    for (int j = 0; j < FF; j++) h[j] = s_b0[j];
    seg32(h, g_acc3 + (size_t)r * FF, s_w0);              // x3[row]
    seg32(h, g_acc2 + (size_t)r * FF, s_w0 + 32 * FF);    // x2[row]
    seg32(h, g_acc3 + (size_t)c * FF, s_w0 + 64 * FF);    // x3[col]
    seg32(h, g_acc2 + (size_t)c * FF, s_w0 + 96 * FF);    // x2[col]
    seg32(h, g_e3 + (size_t)e * FF, s_w0 + 128 * FF);     // e3
    seg32(h, g_e2 + (size_t)e * FF, s_w0 + 160 * FF);     // e2
#pragma unroll
    for (int j = 0; j < FF; j++) h[j] = fmaxf(h[j], 0.f);

    float e4[FF];
#pragma unroll
    for (int j = 0; j < FF; j++) e4[j] = s_b1[j];
#pragma unroll
    for (int k = 0; k < FF; k++) fmarow(e4, h[k], s_w1 + k * FF);
#pragma unroll
    for (int j = 0; j < FF; j++) e4[j] = fmaxf(e4[j], 0.f);

    // head 1: out01 = e4 @ wl01 + bl01 ; edge_x = out01 @ wl1 + bl1 + edge_attr ; normalize
#pragma unroll
    for (int j = 0; j < FF; j++) h[j] = s_b01[j];
#pragma unroll
    for (int k = 0; k < FF; k++) fmarow(h, e4[k], s_w01 + k * FF);

    float4 a = *(const float4*)(ea + (size_t)e * 4);
    float ex0 = s_bl1[0] + a.x, ex1 = s_bl1[1] + a.y, ex2 = s_bl1[2] + a.z, ex3 = s_bl1[3] + a.w;
#pragma unroll
    for (int j = 0; j < FF; j++) {
        float4 w = *(const float4*)(s_wl1 + j * 4);
        ex0 += h[j] * w.x;
        ex1 += h[j] * w.y;
        ex2 += h[j] * w.z;
        ex3 += h[j] * w.w;
    }
    float nrm = sqrtf(ex0 * ex0 + ex1 * ex1 + ex2 * ex2 + ex3 * ex3);
    float inv = 1.0f / fmaxf(nrm, 1e-12f);
    *(float4*)(out + (size_t)EE + (size_t)e * 4) =
        make_float4(ex0 * inv, ex1 * inv, ex2 * inv, ex3 * inv);

    // head 2: probs = sigmoid((e4 @ wl02 + bl02) @ wl2 + bl2)
#pragma unroll
    for (int j = 0; j < FF; j++) h[j] = s_b02[j];
#pragma unroll
    for (int k = 0; k < FF; k++) fmarow(h, e4[k], s_w02 + k * FF);
    float z = s_bl2;
#pragma unroll
    for (int j = 0; j < FF; j++) z += h[j] * s_wl2[j];
    out[e] = 1.0f / (1.0f + expf(-z));
}

// ---------------- launch ----------------
extern "C" void kernel_launch(void* const* d_in, const int* in_sizes, int n_in,
                              void* d_out, int out_size) {
    const int* eidx = (const int*)d_in[1];
    const float* ea = (const float*)d_in[2];
    const float* beta = (const float*)d_in[3];
    const float* w10 = (const float*)d_in[4];
    const float* b10 = (const float*)d_in[5];
    const float* w11 = (const float*)d_in[6];
    const float* b11 = (const float*)d_in[7];
    const float* w20 = (const float*)d_in[8];
    const float* b20 = (const float*)d_in[9];
    const float* w21 = (const float*)d_in[10];
    const float* b21 = (const float*)d_in[11];
    const float* w30 = (const float*)d_in[12];
    const float* b30 = (const float*)d_in[13];
    const float* w31 = (const float*)d_in[14];
    const float* b31 = (const float*)d_in[15];
    const float* w40 = (const float*)d_in[16];
    const float* b40 = (const float*)d_in[17];
    const float* w41 = (const float*)d_in[18];
    const float* b41 = (const float*)d_in[19];
    const float* wl01 = (const float*)d_in[20];
    const float* bl01 = (const float*)d_in[21];
    const float* wl02 = (const float*)d_in[22];
    const float* bl02 = (const float*)d_in[23];
    const float* wl1 = (const float*)d_in[24];
    const float* bl1 = (const float*)d_in[25];
    const float* wl2 = (const float*)d_in[26];
    const float* bl2 = (const float*)d_in[27];
    float* out = (float*)d_out;

    const int T = 256;
    const int gridE = (EE + T - 1) / T;
    const int gridNF = (NN * FF + T - 1) / T;

    k_zero<<<gridNF, T>>>();
    k_beta<<<(3 * NN + T - 1) / T, T>>>(beta, out);
    k_conv1<<<gridE, T>>>(ea, eidx, w10, b10, w11, b11);
    k_final<<<gridNF, T>>>(0);
    k_conv2<<<gridE, T>>>(ea, eidx, w20, b20, w21, b21);
    k_final<<<gridNF, T>>>(1);
    k_conv3<<<gridE, T>>>(eidx, w30, b30, w31, b31);
    k_final<<<gridNF, T>>>(2);
    k_conv4<<<gridE, T>>>(ea, eidx, w40, b40, w41, b41, wl01, bl01, wl02, bl02,
                          wl1, bl1, wl2, bl2, out);
}

// round 2
// speedup vs baseline: 1.1308x; 1.1308x over previous
#include <cuda_runtime.h>
#include <math.h>

#define NN 50000
#define EE 400000
#define FF 32

typedef unsigned long long ull;

// ---------------- scratch (static device arrays; allocation-free) ----------------
__device__ __align__(128) float g_e1[(size_t)EE * FF];
__device__ __align__(128) float g_e2[(size_t)EE * FF];
__device__ __align__(128) float g_e3[(size_t)EE * FF];
__device__ __align__(128) float g_acc1[(size_t)NN * FF];  // becomes x1 after finalize
__device__ __align__(128) float g_acc2[(size_t)NN * FF];  // becomes x2
__device__ __align__(128) float g_acc3[(size_t)NN * FF];  // becomes x3
__device__ __align__(128) float g_cnt[NN];

// ---------------- f32x2 packed-FMA helpers (sm_100a Blackwell) ----------------
__device__ __forceinline__ void ffma2(ull& d, ull a, ull b) {
    asm("fma.rn.f32x2 %0, %1, %2, %0;" : "+l"(d) : "l"(a), "l"(b));
}
__device__ __forceinline__ ull pk2(float v) {  // broadcast scalar into both lanes
    ull r;
    asm("mov.b64 %0, {%1, %1};" : "=l"(r) : "f"(v));
    return r;
}

union V32 {
    float f[FF];
    ull u[FF / 2];
};

// h += v * w_row   (w_row: 32 floats in shared, 16B-aligned)
__device__ __forceinline__ void fmarow2(V32& h, ull v2, const float* __restrict__ wr) {
#pragma unroll
    for (int j = 0; j < 8; j++) {
        ulonglong2 w = *(const ulonglong2*)(wr + j * 4);  // LDS.128 = 4 weights
        ffma2(h.u[2 * j + 0], v2, w.x);
        ffma2(h.u[2 * j + 1], v2, w.y);
    }
}

// accumulate a 32-wide input segment (16B-aligned src) against 32 rows of shared weights
__device__ __forceinline__ void seg32(V32& h, const float* __restrict__ src,
                                      const float* __restrict__ ws) {
#pragma unroll
    for (int k = 0; k < FF; k += 4) {
        float4 v = *(const float4*)(src + k);
        fmarow2(h, pk2(v.x), ws + (k + 0) * FF);
        fmarow2(h, pk2(v.y), ws + (k + 1) * FF);
        fmarow2(h, pk2(v.z), ws + (k + 2) * FF);
        fmarow2(h, pk2(v.w), ws + (k + 3) * FF);
    }
}

__device__ __forceinline__ void cpsh(float* dst, const float* src, int n, int tid, int nt) {
    for (int i = tid; i < n; i += nt) dst[i] = src[i];
}

__device__ __forceinline__ void ldbias(V32& h, const float* __restrict__ b) {
#pragma unroll
    for (int j = 0; j < FF; j++) h.f[j] = b[j];
}
__device__ __forceinline__ void relu32(V32& h) {
#pragma unroll
    for (int j = 0; j < FF; j++) h.f[j] = fmaxf(h.f[j], 0.f);
}
__device__ __forceinline__ void store_relu32(float* __restrict__ dst, const V32& o) {
#pragma unroll
    for (int j = 0; j < FF; j += 4) {
        float4 t = make_float4(fmaxf(o.f[j], 0.f), fmaxf(o.f[j + 1], 0.f),
                               fmaxf(o.f[j + 2], 0.f), fmaxf(o.f[j + 3], 0.f));
        *(float4*)(dst + j) = t;
    }
}
__device__ __forceinline__ void scatter32(float* __restrict__ acc, const V32& o) {
#pragma unroll
    for (int j = 0; j < FF; j++) atomicAdd(acc + j, o.f[j]);
}

// second-layer 32x32 MLP: o = b1 + h @ w1 (w1 in shared)
__device__ __forceinline__ void layer2(V32& o, const V32& h, const float* __restrict__ sw1,
                                       const float* __restrict__ sb1) {
    ldbias(o, sb1);
#pragma unroll
    for (int k = 0; k < FF; k++) fmarow2(o, pk2(h.f[k]), sw1 + k * FF);
}

// ---------------- init / misc kernels ----------------
__global__ void k_init(const float* __restrict__ beta, float* __restrict__ out) {
    int i = blockIdx.x * blockDim.x + threadIdx.x;
    if (i < NN * FF) {
        g_acc1[i] = 0.f;
        g_acc2[i] = 0.f;
        g_acc3[i] = 0.f;
    }
    if (i < NN) g_cnt[i] = 0.f;
    if (i < 3 * NN) out[(size_t)5 * EE + i] = beta[i];
}

__global__ void k_final(int which) {
    int i = blockIdx.x * blockDim.x + threadIdx.x;
    if (i >= NN * FF) return;
    float* acc = (which == 0) ? g_acc1 : (which == 1) ? g_acc2 : g_acc3;
    float c = fmaxf(g_cnt[i >> 5], 1.0f);
    acc[i] = fmaxf(acc[i] / c, 0.0f);
}

// ---------------- conv1 ----------------
__global__ void k_conv1(const float* __restrict__ ea, const int* __restrict__ eidx,
                        const float* __restrict__ w10, const float* __restrict__ b10,
                        const float* __restrict__ w11, const float* __restrict__ b11) {
    __shared__ __align__(16) float s_w0[4 * FF];
    __shared__ __align__(16) float s_b0[FF];
    __shared__ __align__(16) float s_w1[FF * FF];
    __shared__ __align__(16) float s_b1[FF];
    int tid = threadIdx.x, nt = blockDim.x;
    cpsh(s_w0, w10, 4 * FF, tid, nt);
    cpsh(s_b0, b10, FF, tid, nt);
    cpsh(s_w1, w11, FF * FF, tid, nt);
    cpsh(s_b1, b11, FF, tid, nt);
    __syncthreads();

    int e = blockIdx.x * nt + tid;
    if (e >= EE) return;

    float4 a = *(const float4*)(ea + (size_t)e * 4);
    V32 h;
    ldbias(h, s_b0);
    fmarow2(h, pk2(a.x), s_w0);
    fmarow2(h, pk2(a.y), s_w0 + FF);
    fmarow2(h, pk2(a.z), s_w0 + 2 * FF);
    fmarow2(h, pk2(a.w), s_w0 + 3 * FF);
    relu32(h);

    V32 o;
    layer2(o, h, s_w1, s_b1);

    int r = eidx[e];
    scatter32(g_acc1 + (size_t)r * FF, o);
    atomicAdd(&g_cnt[r], 1.0f);
    store_relu32(g_e1 + (size_t)e * FF, o);
}

// ---------------- conv2: in = [x1[r], x1[c], edge_attr, e1] (100) ----------------
__global__ void k_conv2(const float* __restrict__ ea, const int* __restrict__ eidx,
                        const float* __restrict__ w20, const float* __restrict__ b20,
                        const float* __restrict__ w21, const float* __restrict__ b21) {
    __shared__ __align__(16) float s_w0[100 * FF];
    __shared__ __align__(16) float s_b0[FF];
    __shared__ __align__(16) float s_w1[FF * FF];
    __shared__ __align__(16) float s_b1[FF];
    int tid = threadIdx.x, nt = blockDim.x;
    cpsh(s_w0, w20, 100 * FF, tid, nt);
    cpsh(s_b0, b20, FF, tid, nt);
    cpsh(s_w1, w21, FF * FF, tid, nt);
    cpsh(s_b1, b21, FF, tid, nt);
    __syncthreads();

    int e = blockIdx.x * nt + tid;
    if (e >= EE) return;

    int r = eidx[e], c = eidx[EE + e];
    V32 h;
    ldbias(h, s_b0);
    seg32(h, g_acc1 + (size_t)r * FF, s_w0);            // rows 0..31 : x1[row]
    seg32(h, g_acc1 + (size_t)c * FF, s_w0 + 32 * FF);  // rows 32..63: x1[col]
    float4 a = *(const float4*)(ea + (size_t)e * 4);    // rows 64..67: edge_attr
    fmarow2(h, pk2(a.x), s_w0 + 64 * FF);
    fmarow2(h, pk2(a.y), s_w0 + 65 * FF);
    fmarow2(h, pk2(a.z), s_w0 + 66 * FF);
    fmarow2(h, pk2(a.w), s_w0 + 67 * FF);
    seg32(h, g_e1 + (size_t)e * FF, s_w0 + 68 * FF);    // rows 68..99: e1
    relu32(h);

    V32 o;
    layer2(o, h, s_w1, s_b1);

    scatter32(g_acc2 + (size_t)r * FF, o);
    store_relu32(g_e2 + (size_t)e * FF, o);
}

// ---------------- conv3: in = [x2[r], x1[r], x2[c], x1[c], e2, e1] (192) ----------------
__global__ void k_conv3(const int* __restrict__ eidx,
                        const float* __restrict__ w30, const float* __restrict__ b30,
                        const float* __restrict__ w31, const float* __restrict__ b31) {
    __shared__ __align__(16) float s_w0[192 * FF];
    __shared__ __align__(16) float s_b0[FF];
    __shared__ __align__(16) float s_w1[FF * FF];
    __shared__ __align__(16) float s_b1[FF];
    int tid = threadIdx.x, nt = blockDim.x;
    cpsh(s_w0, w30, 192 * FF, tid, nt);
    cpsh(s_b0, b30, FF, tid, nt);
    cpsh(s_w1, w31, FF * FF, tid, nt);
    cpsh(s_b1, b31, FF, tid, nt);
    __syncthreads();

    int e = blockIdx.x * nt + tid;
    if (e >= EE) return;

    int r = eidx[e], c = eidx[EE + e];
    V32 h;
    ldbias(h, s_b0);
    seg32(h, g_acc2 + (size_t)r * FF, s_w0);             // x2[row]
    seg32(h, g_acc1 + (size_t)r * FF, s_w0 + 32 * FF);   // x1[row]
    seg32(h, g_acc2 + (size_t)c * FF, s_w0 + 64 * FF);   // x2[col]
    seg32(h, g_acc1 + (size_t)c * FF, s_w0 + 96 * FF);   // x1[col]
    seg32(h, g_e2 + (size_t)e * FF, s_w0 + 128 * FF);    // e2
    seg32(h, g_e1 + (size_t)e * FF, s_w0 + 160 * FF);    // e1
    relu32(h);

    V32 o;
    layer2(o, h, s_w1, s_b1);

    scatter32(g_acc3 + (size_t)r * FF, o);
    store_relu32(g_e3 + (size_t)e * FF, o);
}

// ---------------- conv4 + heads fused ----------------
__global__ void k_conv4(const float* __restrict__ ea, const int* __restrict__ eidx,
                        const float* __restrict__ w40, const float* __restrict__ b40,
                        const float* __restrict__ w41, const float* __restrict__ b41,
                        const float* __restrict__ wl01, const float* __restrict__ bl01,
                        const float* __restrict__ wl02, const float* __restrict__ bl02,
                        const float* __restrict__ wl1, const float* __restrict__ bl1,
                        const float* __restrict__ wl2, const float* __restrict__ bl2,
                        float* __restrict__ out) {
    __shared__ __align__(16) float s_w0[192 * FF];
    __shared__ __align__(16) float s_b0[FF];
    __shared__ __align__(16) float s_w1[FF * FF];
    __shared__ __align__(16) float s_b1[FF];
    __shared__ __align__(16) float s_w01[FF * FF];
    __shared__ __align__(16) float s_b01[FF];
    __shared__ __align__(16) float s_w02[FF * FF];
    __shared__ __align__(16) float s_b02[FF];
    __shared__ __align__(16) float s_wl1[FF * 4];
    __shared__ __align__(16) float s_wl2[FF];
    __shared__ float s_bl1[4];
    __shared__ float s_bl2;
    int tid = threadIdx.x, nt = blockDim.x;
    cpsh(s_w0, w40, 192 * FF, tid, nt);
    cpsh(s_b0, b40, FF, tid, nt);
    cpsh(s_w1, w41, FF * FF, tid, nt);
    cpsh(s_b1, b41, FF, tid, nt);
    cpsh(s_w01, wl01, FF * FF, tid, nt);
    cpsh(s_b01, bl01, FF, tid, nt);
    cpsh(s_w02, wl02, FF * FF, tid, nt);
    cpsh(s_b02, bl02, FF, tid, nt);
    cpsh(s_wl1, wl1, FF * 4, tid, nt);
    cpsh(s_wl2, wl2, FF, tid, nt);
    if (tid < 4) s_bl1[tid] = bl1[tid];
    if (tid == 0) s_bl2 = bl2[0];
    __syncthreads();

    int e = blockIdx.x * nt + tid;
    if (e >= EE) return;

    int r = eidx[e], c = eidx[EE + e];
    V32 h;
    ldbias(h, s_b0);
    seg32(h, g_acc3 + (size_t)r * FF, s_w0);             // x3[row]
    seg32(h, g_acc2 + (size_t)r * FF, s_w0 + 32 * FF);   // x2[row]
    seg32(h, g_acc3 + (size_t)c * FF, s_w0 + 64 * FF);   // x3[col]
    seg32(h, g_acc2 + (size_t)c * FF, s_w0 + 96 * FF);   // x2[col]
    seg32(h, g_e3 + (size_t)e * FF, s_w0 + 128 * FF);    // e3
    seg32(h, g_e2 + (size_t)e * FF, s_w0 + 160 * FF);    // e2
    relu32(h);

    V32 e4;
    layer2(e4, h, s_w1, s_b1);
    relu32(e4);

    // head 1: out01 = e4 @ wl01 + bl01 ; edge_x = out01 @ wl1 + bl1 + edge_attr ; normalize
    layer2(h, e4, s_w01, s_b01);

    float4 a = *(const float4*)(ea + (size_t)e * 4);
    float ex0 = s_bl1[0] + a.x, ex1 = s_bl1[1] + a.y, ex2 = s_bl1[2] + a.z, ex3 = s_bl1[3] + a.w;
#pragma unroll
    for (int j = 0; j < FF; j++) {
        float4 w = *(const float4*)(s_wl1 + j * 4);
        ex0 += h.f[j] * w.x;
        ex1 += h.f[j] * w.y;
        ex2 += h.f[j] * w.z;
        ex3 += h.f[j] * w.w;
    }
    float nrm = sqrtf(ex0 * ex0 + ex1 * ex1 + ex2 * ex2 + ex3 * ex3);
    float inv = 1.0f / fmaxf(nrm, 1e-12f);
    *(float4*)(out + (size_t)EE + (size_t)e * 4) =
        make_float4(ex0 * inv, ex1 * inv, ex2 * inv, ex3 * inv);

    // head 2: probs = sigmoid((e4 @ wl02 + bl02) @ wl2 + bl2)
    layer2(h, e4, s_w02, s_b02);
    float z = s_bl2;
#pragma unroll
    for (int j = 0; j < FF; j++) z += h.f[j] * s_wl2[j];
    out[e] = 1.0f / (1.0f + expf(-z));
}

// ---------------- launch ----------------
extern "C" void kernel_launch(void* const* d_in, const int* in_sizes, int n_in,
                              void* d_out, int out_size) {
    const int* eidx = (const int*)d_in[1];
    const float* ea = (const float*)d_in[2];
    const float* beta = (const float*)d_in[3];
    const float* w10 = (const float*)d_in[4];
    const float* b10 = (const float*)d_in[5];
    const float* w11 = (const float*)d_in[6];
    const float* b11 = (const float*)d_in[7];
    const float* w20 = (const float*)d_in[8];
    const float* b20 = (const float*)d_in[9];
    const float* w21 = (const float*)d_in[10];
    const float* b21 = (const float*)d_in[11];
    const float* w30 = (const float*)d_in[12];
    const float* b30 = (const float*)d_in[13];
    const float* w31 = (const float*)d_in[14];
    const float* b31 = (const float*)d_in[15];
    const float* w40 = (const float*)d_in[16];
    const float* b40 = (const float*)d_in[17];
    const float* w41 = (const float*)d_in[18];
    const float* b41 = (const float*)d_in[19];
    const float* wl01 = (const float*)d_in[20];
    const float* bl01 = (const float*)d_in[21];
    const float* wl02 = (const float*)d_in[22];
    const float* bl02 = (const float*)d_in[23];
    const float* wl1 = (const float*)d_in[24];
    const float* bl1 = (const float*)d_in[25];
    const float* wl2 = (const float*)d_in[26];
    const float* bl2 = (const float*)d_in[27];
    float* out = (float*)d_out;

    const int T = 256;
    const int gridE = (EE + T - 1) / T;
    const int gridNF = (NN * FF + T - 1) / T;

    k_init<<<gridNF, T>>>(beta, out);
    k_conv1<<<gridE, T>>>(ea, eidx, w10, b10, w11, b11);
    k_final<<<gridNF, T>>>(0);
    k_conv2<<<gridE, T>>>(ea, eidx, w20, b20, w21, b21);
    k_final<<<gridNF, T>>>(1);
    k_conv3<<<gridE, T>>>(eidx, w30, b30, w31, b31);
    k_final<<<gridNF, T>>>(2);
    k_conv4<<<gridE, T>>>(ea, eidx, w40, b40, w41, b41, wl01, bl01, wl02, bl02,
                          wl1, bl1, wl2, bl2, out);
}

// round 3
// speedup vs baseline: 1.4058x; 1.2432x over previous
#include <cuda_runtime.h>
#include <math.h>

#define NN 50000
#define EE 400000
#define FF 32
#define HALF_E (EE / 2)

typedef unsigned long long ull;

// ---------------- scratch (static device arrays; allocation-free) ----------------
__device__ __align__(128) float g_e1[(size_t)EE * FF];
__device__ __align__(128) float g_e2[(size_t)EE * FF];
__device__ __align__(128) float g_e3[(size_t)EE * FF];
__device__ __align__(128) float g_acc1[(size_t)NN * FF];  // becomes x1 after finalize
__device__ __align__(128) float g_acc2[(size_t)NN * FF];  // becomes x2
__device__ __align__(128) float g_acc3[(size_t)NN * FF];  // becomes x3
__device__ __align__(128) float g_cnt[NN];

// ---------------- f32x2 packed-FMA helpers (sm_100a) ----------------
__device__ __forceinline__ void ffma2(ull& d, ull a, ull b) {
    asm("fma.rn.f32x2 %0, %1, %2, %0;" : "+l"(d) : "l"(a), "l"(b));
}
__device__ __forceinline__ ull pk2(float v) {
    ull r;
    asm("mov.b64 %0, {%1, %1};" : "=l"(r) : "f"(v));
    return r;
}

union V32 {
    float f[FF];
    ull u[FF / 2];
};

// two edges share each weight load: 1 LDS.128 feeds 4 ffma2
__device__ __forceinline__ void fmarow2p(V32& h0, V32& h1, ull v0, ull v1,
                                         const float* __restrict__ wr) {
#pragma unroll
    for (int j = 0; j < 8; j++) {
        ulonglong2 w = *(const ulonglong2*)(wr + j * 4);
        ffma2(h0.u[2 * j + 0], v0, w.x);
        ffma2(h0.u[2 * j + 1], v0, w.y);
        ffma2(h1.u[2 * j + 0], v1, w.x);
        ffma2(h1.u[2 * j + 1], v1, w.y);
    }
}

// 32-wide input segment for an edge pair
__device__ __forceinline__ void seg32p(V32& h0, V32& h1, const float* __restrict__ s0,
                                       const float* __restrict__ s1,
                                       const float* __restrict__ ws) {
#pragma unroll
    for (int k = 0; k < FF; k += 4) {
        float4 a = *(const float4*)(s0 + k);
        float4 b = *(const float4*)(s1 + k);
        fmarow2p(h0, h1, pk2(a.x), pk2(b.x), ws + (k + 0) * FF);
        fmarow2p(h0, h1, pk2(a.y), pk2(b.y), ws + (k + 1) * FF);
        fmarow2p(h0, h1, pk2(a.z), pk2(b.z), ws + (k + 2) * FF);
        fmarow2p(h0, h1, pk2(a.w), pk2(b.w), ws + (k + 3) * FF);
    }
}

__device__ __forceinline__ void cpsh(float* dst, const float* src, int n, int tid, int nt) {
    for (int i = tid; i < n; i += nt) dst[i] = src[i];
}
__device__ __forceinline__ void ldbias(V32& h, const float* __restrict__ b) {
#pragma unroll
    for (int j = 0; j < FF; j++) h.f[j] = b[j];
}
__device__ __forceinline__ void relu32(V32& h) {
#pragma unroll
    for (int j = 0; j < FF; j++) h.f[j] = fmaxf(h.f[j], 0.f);
}
__device__ __forceinline__ void store_relu32(float* __restrict__ dst, const V32& o) {
#pragma unroll
    for (int j = 0; j < FF; j += 4) {
        float4 t = make_float4(fmaxf(o.f[j], 0.f), fmaxf(o.f[j + 1], 0.f),
                               fmaxf(o.f[j + 2], 0.f), fmaxf(o.f[j + 3], 0.f));
        *(float4*)(dst + j) = t;
    }
}
__device__ __forceinline__ void red4(float* __restrict__ a, float x, float y, float z, float w) {
    asm volatile("red.global.add.v4.f32 [%0], {%1, %2, %3, %4};" ::"l"(a), "f"(x), "f"(y),
                 "f"(z), "f"(w)
                 : "memory");
}
__device__ __forceinline__ void scatter32(float* __restrict__ acc, const V32& o) {
#pragma unroll
    for (int j = 0; j < FF; j += 4) red4(acc + j, o.f[j], o.f[j + 1], o.f[j + 2], o.f[j + 3]);
}

// joint second layer: o{0,1} = b1 + h{0,1} @ w1  (weight loads shared)
__device__ __forceinline__ void layer2p(V32& o0, V32& o1, const V32& h0, const V32& h1,
                                        const float* __restrict__ sw1,
                                        const float* __restrict__ sb1) {
    ldbias(o0, sb1);
    ldbias(o1, sb1);
#pragma unroll
    for (int k = 0; k < FF; k++)
        fmarow2p(o0, o1, pk2(h0.f[k]), pk2(h1.f[k]), sw1 + k * FF);
}

// ---------------- init / finalize ----------------
__global__ void k_init(const float* __restrict__ beta, float* __restrict__ out) {
    int i = blockIdx.x * blockDim.x + threadIdx.x;
    if (i < NN * FF) {
        g_acc1[i] = 0.f;
        g_acc2[i] = 0.f;
        g_acc3[i] = 0.f;
    }
    if (i < NN) g_cnt[i] = 0.f;
    if (i < 3 * NN) out[(size_t)5 * EE + i] = beta[i];
}

__global__ void k_final(int which) {
    int i = blockIdx.x * blockDim.x + threadIdx.x;
    if (i >= NN * FF) return;
    float* acc = (which == 0) ? g_acc1 : (which == 1) ? g_acc2 : g_acc3;
    float c = fmaxf(g_cnt[i >> 5], 1.0f);
    acc[i] = fmaxf(acc[i] / c, 0.0f);
}

// ---------------- conv1 ----------------
__global__ __launch_bounds__(128) void k_conv1(const float* __restrict__ ea,
                                               const int* __restrict__ eidx,
                                               const float* __restrict__ w10,
                                               const float* __restrict__ b10,
                                               const float* __restrict__ w11,
                                               const float* __restrict__ b11) {
    __shared__ __align__(16) float s_w0[4 * FF];
    __shared__ __align__(16) float s_b0[FF];
    __shared__ __align__(16) float s_w1[FF * FF];
    __shared__ __align__(16) float s_b1[FF];
    int tid = threadIdx.x, nt = blockDim.x;
    cpsh(s_w0, w10, 4 * FF, tid, nt);
    cpsh(s_b0, b10, FF, tid, nt);
    cpsh(s_w1, w11, FF * FF, tid, nt);
    cpsh(s_b1, b11, FF, tid, nt);
    __syncthreads();

    int p = blockIdx.x * nt + tid;
    if (p >= HALF_E) return;
    int e0 = 2 * p, e1 = 2 * p + 1;

    float4 a0 = *(const float4*)(ea + (size_t)e0 * 4);
    float4 a1 = *(const float4*)(ea + (size_t)e1 * 4);
    V32 h0, h1;
    ldbias(h0, s_b0);
    ldbias(h1, s_b0);
    fmarow2p(h0, h1, pk2(a0.x), pk2(a1.x), s_w0);
    fmarow2p(h0, h1, pk2(a0.y), pk2(a1.y), s_w0 + FF);
    fmarow2p(h0, h1, pk2(a0.z), pk2(a1.z), s_w0 + 2 * FF);
    fmarow2p(h0, h1, pk2(a0.w), pk2(a1.w), s_w0 + 3 * FF);
    relu32(h0);
    relu32(h1);

    V32 o0, o1;
    layer2p(o0, o1, h0, h1, s_w1, s_b1);

    int r0 = eidx[e0], r1 = eidx[e1];
    scatter32(g_acc1 + (size_t)r0 * FF, o0);
    scatter32(g_acc1 + (size_t)r1 * FF, o1);
    atomicAdd(&g_cnt[r0], 1.0f);
    atomicAdd(&g_cnt[r1], 1.0f);
    store_relu32(g_e1 + (size_t)e0 * FF, o0);
    store_relu32(g_e1 + (size_t)e1 * FF, o1);
}

// ---------------- conv2: in = [x1[r], x1[c], edge_attr, e1] (100) ----------------
__global__ __launch_bounds__(128) void k_conv2(const float* __restrict__ ea,
                                               const int* __restrict__ eidx,
                                               const float* __restrict__ w20,
                                               const float* __restrict__ b20,
                                               const float* __restrict__ w21,
                                               const float* __restrict__ b21) {
    __shared__ __align__(16) float s_w0[100 * FF];
    __shared__ __align__(16) float s_b0[FF];
    __shared__ __align__(16) float s_w1[FF * FF];
    __shared__ __align__(16) float s_b1[FF];
    int tid = threadIdx.x, nt = blockDim.x;
    cpsh(s_w0, w20, 100 * FF, tid, nt);
    cpsh(s_b0, b20, FF, tid, nt);
    cpsh(s_w1, w21, FF * FF, tid, nt);
    cpsh(s_b1, b21, FF, tid, nt);
    __syncthreads();

    int p = blockIdx.x * nt + tid;
    if (p >= HALF_E) return;
    int e0 = 2 * p, e1 = 2 * p + 1;

    int r0 = eidx[e0], c0 = eidx[EE + e0];
    int r1 = eidx[e1], c1 = eidx[EE + e1];
    V32 h0, h1;
    ldbias(h0, s_b0);
    ldbias(h1, s_b0);
    seg32p(h0, h1, g_acc1 + (size_t)r0 * FF, g_acc1 + (size_t)r1 * FF, s_w0);
    seg32p(h0, h1, g_acc1 + (size_t)c0 * FF, g_acc1 + (size_t)c1 * FF, s_w0 + 32 * FF);
    float4 a0 = *(const float4*)(ea + (size_t)e0 * 4);
    float4 a1 = *(const float4*)(ea + (size_t)e1 * 4);
    fmarow2p(h0, h1, pk2(a0.x), pk2(a1.x), s_w0 + 64 * FF);
    fmarow2p(h0, h1, pk2(a0.y), pk2(a1.y), s_w0 + 65 * FF);
    fmarow2p(h0, h1, pk2(a0.z), pk2(a1.z), s_w0 + 66 * FF);
    fmarow2p(h0, h1, pk2(a0.w), pk2(a1.w), s_w0 + 67 * FF);
    seg32p(h0, h1, g_e1 + (size_t)e0 * FF, g_e1 + (size_t)e1 * FF, s_w0 + 68 * FF);
    relu32(h0);
    relu32(h1);

    V32 o0, o1;
    layer2p(o0, o1, h0, h1, s_w1, s_b1);

    scatter32(g_acc2 + (size_t)r0 * FF, o0);
    scatter32(g_acc2 + (size_t)r1 * FF, o1);
    store_relu32(g_e2 + (size_t)e0 * FF, o0);
    store_relu32(g_e2 + (size_t)e1 * FF, o1);
}

// ---------------- conv3: in = [x2[r], x1[r], x2[c], x1[c], e2, e1] (192) ----------------
__global__ __launch_bounds__(128) void k_conv3(const int* __restrict__ eidx,
                                               const float* __restrict__ w30,
                                               const float* __restrict__ b30,
                                               const float* __restrict__ w31,
                                               const float* __restrict__ b31) {
    __shared__ __align__(16) float s_w0[192 * FF];
    __shared__ __align__(16) float s_b0[FF];
    __shared__ __align__(16) float s_w1[FF * FF];
    __shared__ __align__(16) float s_b1[FF];
    int tid = threadIdx.x, nt = blockDim.x;
    cpsh(s_w0, w30, 192 * FF, tid, nt);
    cpsh(s_b0, b30, FF, tid, nt);
    cpsh(s_w1, w31, FF * FF, tid, nt);
    cpsh(s_b1, b31, FF, tid, nt);
    __syncthreads();

    int p = blockIdx.x * nt + tid;
    if (p >= HALF_E) return;
    int e0 = 2 * p, e1 = 2 * p + 1;

    int r0 = eidx[e0], c0 = eidx[EE + e0];
    int r1 = eidx[e1], c1 = eidx[EE + e1];
    V32 h0, h1;
    ldbias(h0, s_b0);
    ldbias(h1, s_b0);
    seg32p(h0, h1, g_acc2 + (size_t)r0 * FF, g_acc2 + (size_t)r1 * FF, s_w0);
    seg32p(h0, h1, g_acc1 + (size_t)r0 * FF, g_acc1 + (size_t)r1 * FF, s_w0 + 32 * FF);
    seg32p(h0, h1, g_acc2 + (size_t)c0 * FF, g_acc2 + (size_t)c1 * FF, s_w0 + 64 * FF);
    seg32p(h0, h1, g_acc1 + (size_t)c0 * FF, g_acc1 + (size_t)c1 * FF, s_w0 + 96 * FF);
    seg32p(h0, h1, g_e2 + (size_t)e0 * FF, g_e2 + (size_t)e1 * FF, s_w0 + 128 * FF);
    seg32p(h0, h1, g_e1 + (size_t)e0 * FF, g_e1 + (size_t)e1 * FF, s_w0 + 160 * FF);
    relu32(h0);
    relu32(h1);

    V32 o0, o1;
    layer2p(o0, o1, h0, h1, s_w1, s_b1);

    scatter32(g_acc3 + (size_t)r0 * FF, o0);
    scatter32(g_acc3 + (size_t)r1 * FF, o1);
    store_relu32(g_e3 + (size_t)e0 * FF, o0);
    store_relu32(g_e3 + (size_t)e1 * FF, o1);
}

// ---------------- conv4 + heads fused ----------------
__global__ __launch_bounds__(128) void k_conv4(
    const float* __restrict__ ea, const int* __restrict__ eidx,
    const float* __restrict__ w40, const float* __restrict__ b40,
    const float* __restrict__ w41, const float* __restrict__ b41,
    const float* __restrict__ wl01, const float* __restrict__ bl01,
    const float* __restrict__ wl02, const float* __restrict__ bl02,
    const float* __restrict__ wl1, const float* __restrict__ bl1,
    const float* __restrict__ wl2, const float* __restrict__ bl2, float* __restrict__ out) {
    __shared__ __align__(16) float s_w0[192 * FF];
    __shared__ __align__(16) float s_b0[FF];
    __shared__ __align__(16) float s_w1[FF * FF];
    __shared__ __align__(16) float s_b1[FF];
    __shared__ __align__(16) float s_w01[FF * FF];
    __shared__ __align__(16) float s_b01[FF];
    __shared__ __align__(16) float s_w02[FF * FF];
    __shared__ __align__(16) float s_b02[FF];
    __shared__ __align__(16) float s_wl1[FF * 4];
    __shared__ __align__(16) float s_wl2[FF];
    __shared__ float s_bl1[4];
    __shared__ float s_bl2;
    int tid = threadIdx.x, nt = blockDim.x;
    cpsh(s_w0, w40, 192 * FF, tid, nt);
    cpsh(s_b0, b40, FF, tid, nt);
    cpsh(s_w1, w41, FF * FF, tid, nt);
    cpsh(s_b1, b41, FF, tid, nt);
    cpsh(s_w01, wl01, FF * FF, tid, nt);
    cpsh(s_b01, bl01, FF, tid, nt);
    cpsh(s_w02, wl02, FF * FF, tid, nt);
    cpsh(s_b02, bl02, FF, tid, nt);
    cpsh(s_wl1, wl1, FF * 4, tid, nt);
    cpsh(s_wl2, wl2, FF, tid, nt);
    if (tid < 4) s_bl1[tid] = bl1[tid];
    if (tid == 0) s_bl2 = bl2[0];
    __syncthreads();

    int p = blockIdx.x * nt + tid;
    if (p >= HALF_E) return;
    int e0 = 2 * p, e1 = 2 * p + 1;

    int r0 = eidx[e0], c0 = eidx[EE + e0];
    int r1 = eidx[e1], c1 = eidx[EE + e1];
    V32 h0, h1;
    ldbias(h0, s_b0);
    ldbias(h1, s_b0);
    seg32p(h0, h1, g_acc3 + (size_t)r0 * FF, g_acc3 + (size_t)r1 * FF, s_w0);
    seg32p(h0, h1, g_acc2 + (size_t)r0 * FF, g_acc2 + (size_t)r1 * FF, s_w0 + 32 * FF);
    seg32p(h0, h1, g_acc3 + (size_t)c0 * FF, g_acc3 + (size_t)c1 * FF, s_w0 + 64 * FF);
    seg32p(h0, h1, g_acc2 + (size_t)c0 * FF, g_acc2 + (size_t)c1 * FF, s_w0 + 96 * FF);
    seg32p(h0, h1, g_e3 + (size_t)e0 * FF, g_e3 + (size_t)e1 * FF, s_w0 + 128 * FF);
    seg32p(h0, h1, g_e2 + (size_t)e0 * FF, g_e2 + (size_t)e1 * FF, s_w0 + 160 * FF);
    relu32(h0);
    relu32(h1);

    V32 e40, e41;
    layer2p(e40, e41, h0, h1, s_w1, s_b1);
    relu32(e40);
    relu32(e41);

    // head 1: out01 = e4 @ wl01 + bl01 ; edge_x = out01 @ wl1 + bl1 + edge_attr ; normalize
    layer2p(h0, h1, e40, e41, s_w01, s_b01);

#pragma unroll
    for (int side = 0; side < 2; side++) {
        const V32& hh = side ? h1 : h0;
        int e = side ? e1 : e0;
        float4 a = *(const float4*)(ea + (size_t)e * 4);
        float ex0 = s_bl1[0] + a.x, ex1 = s_bl1[1] + a.y;
        float ex2 = s_bl1[2] + a.z, ex3 = s_bl1[3] + a.w;
#pragma unroll
        for (int j = 0; j < FF; j++) {
            float4 w = *(const float4*)(s_wl1 + j * 4);
            ex0 += hh.f[j] * w.x;
            ex1 += hh.f[j] * w.y;
            ex2 += hh.f[j] * w.z;
            ex3 += hh.f[j] * w.w;
        }
        float nrm = sqrtf(ex0 * ex0 + ex1 * ex1 + ex2 * ex2 + ex3 * ex3);
        float inv = 1.0f / fmaxf(nrm, 1e-12f);
        *(float4*)(out + (size_t)EE + (size_t)e * 4) =
            make_float4(ex0 * inv, ex1 * inv, ex2 * inv, ex3 * inv);
    }

    // head 2: probs = sigmoid((e4 @ wl02 + bl02) @ wl2 + bl2)
    layer2p(h0, h1, e40, e41, s_w02, s_b02);
#pragma unroll
    for (int side = 0; side < 2; side++) {
        const V32& hh = side ? h1 : h0;
        int e = side ? e1 : e0;
        float z = s_bl2;
#pragma unroll
        for (int j = 0; j < FF; j++) z += hh.f[j] * s_wl2[j];
        out[e] = 1.0f / (1.0f + expf(-z));
    }
}

// ---------------- launch ----------------
extern "C" void kernel_launch(void* const* d_in, const int* in_sizes, int n_in,
                              void* d_out, int out_size) {
    const int* eidx = (const int*)d_in[1];
    const float* ea = (const float*)d_in[2];
    const float* beta = (const float*)d_in[3];
    const float* w10 = (const float*)d_in[4];
    const float* b10 = (const float*)d_in[5];
    const float* w11 = (const float*)d_in[6];
    const float* b11 = (const float*)d_in[7];
    const float* w20 = (const float*)d_in[8];
    const float* b20 = (const float*)d_in[9];
    const float* w21 = (const float*)d_in[10];
    const float* b21 = (const float*)d_in[11];
    const float* w30 = (const float*)d_in[12];
    const float* b30 = (const float*)d_in[13];
    const float* w31 = (const float*)d_in[14];
    const float* b31 = (const float*)d_in[15];
    const float* w40 = (const float*)d_in[16];
    const float* b40 = (const float*)d_in[17];
    const float* w41 = (const float*)d_in[18];
    const float* b41 = (const float*)d_in[19];
    const float* wl01 = (const float*)d_in[20];
    const float* bl01 = (const float*)d_in[21];
    const float* wl02 = (const float*)d_in[22];
    const float* bl02 = (const float*)d_in[23];
    const float* wl1 = (const float*)d_in[24];
    const float* bl1 = (const float*)d_in[25];
    const float* wl2 = (const float*)d_in[26];
    const float* bl2 = (const float*)d_in[27];
    float* out = (float*)d_out;

    const int T = 256;
    const int gridNF = (NN * FF + T - 1) / T;
    const int TB = 128;
    const int gridE2 = (HALF_E + TB - 1) / TB;

    k_init<<<gridNF, T>>>(beta, out);
    k_conv1<<<gridE2, TB>>>(ea, eidx, w10, b10, w11, b11);
    k_final<<<gridNF, T>>>(0);
    k_conv2<<<gridE2, TB>>>(ea, eidx, w20, b20, w21, b21);
    k_final<<<gridNF, T>>>(1);
    k_conv3<<<gridE2, TB>>>(eidx, w30, b30, w31, b31);
    k_final<<<gridNF, T>>>(2);
    k_conv4<<<gridE2, TB>>>(ea, eidx, w40, b40, w41, b41, wl01, bl01, wl02, bl02,
                            wl1, bl1, wl2, bl2, out);
}